// round 3
// baseline (speedup 1.0000x reference)
#include <cuda_runtime.h>
#include <math.h>
#include <stdint.h>

#define Bn 131072
#define Dd 256
#define Hh 256
#define Cc 8

// ---------------- scratch (no allocs allowed) ----------------
__device__ int g_cnt[Cc];            // per-expert routed count
__device__ int g_idx[Cc * Bn];       // per-expert compacted sample indices

__global__ void zero_cnt_kernel() {
    if (threadIdx.x < Cc) g_cnt[threadIdx.x] = 0;
}

// Packed fp32x2 FMA: acc.lo += a.lo*b.lo ; acc.hi += a.hi*b.hi (exact fp32)
#define FMA2(acc, a, b) \
    asm("fma.rn.f32x2 %0, %1, %2, %0;" : "+l"(acc) : "l"(a), "l"(b))
#define UNPACK2(lo, hi, v) \
    asm("mov.b64 {%0, %1}, %2;" : "=f"(lo), "=f"(hi) : "l"(v))

// ---------------------------------------------------------------------------
// 64x256 fp32 GEMM tile via FFMA2: Out[rows,256] = relu(A[rows,256]@W + bias)
// BM=64, BN=256 (full width), BK=16, 256 threads, 8 rows x 8 cols per thread.
// A stored duplicated (float2(v,v)) in smem so the broadcast operand of the
// packed FMA loads directly as a b64 pair; B pairs are natural register pairs
// out of the conflict-free LDS.128 pattern from the fp32 version.
// ---------------------------------------------------------------------------
template<bool GATHER>
__global__ __launch_bounds__(256, 2)
void gemm64x256_relu(const float* A,
                     const float* __restrict__ Wall,
                     const float* __restrict__ ball,
                     float* Out)
{
    __shared__ float2 As[16][64];      // duplicated pairs (v,v)
    __shared__ float  Bs[16][256];
    __shared__ int    ridx[64];

    const int tid   = threadIdx.x;
    const int mBase = blockIdx.y * 64;

    const float* W;
    const float* bias;
    if (GATHER) {
        const int c   = blockIdx.z;
        const int cnt = g_cnt[c];
        if (mBase >= cnt) return;
        if (tid < 64) {
            int gi = mBase + tid;
            ridx[tid] = (gi < cnt) ? g_idx[c * Bn + gi] : -1;
        }
        W    = Wall + (size_t)c * Hh * Hh;
        bias = ball + c * Hh;
        __syncthreads();
    } else {
        W    = Wall;
        bias = ball;
    }

    const int tx = tid & 31;   // n-dir: cols tx*4..+3 and 128+tx*4..+3
    const int ty = tid >> 5;   // m-dir: rows ty*8..+7

    // A-tile load mapping: one float4 per thread per k-block
    const int arow = tid >> 2;           // 0..63
    const int ac4  = (tid & 3) * 4;      // 0,4,8,12
    const int grow = GATHER ? ridx[arow] : (mBase + arow);
    const bool a_ok = (!GATHER) || (grow >= 0);
    const float* aptr = A + (size_t)(a_ok ? grow : 0) * 256 + ac4;

    // acc: 8 rows x 4 col-pairs (cols {4tx+0,1},{4tx+2,3},{128+4tx+0,1},{128+4tx+2,3})
    unsigned long long acc2[8][4];
    #pragma unroll
    for (int i = 0; i < 8; i++)
        #pragma unroll
        for (int p = 0; p < 4; p++) acc2[i][p] = 0ull;

    for (int kb = 0; kb < 256; kb += 16) {
        float4 av = make_float4(0.f, 0.f, 0.f, 0.f);
        if (a_ok) av = *(const float4*)(aptr + kb);
        As[ac4 + 0][arow] = make_float2(av.x, av.x);
        As[ac4 + 1][arow] = make_float2(av.y, av.y);
        As[ac4 + 2][arow] = make_float2(av.z, av.z);
        As[ac4 + 3][arow] = make_float2(av.w, av.w);
        #pragma unroll
        for (int i = 0; i < 4; i++) {
            int v  = tid + i * 256;
            int br = v >> 6;
            int bc = (v & 63) * 4;
            *(float4*)&Bs[br][bc] = *(const float4*)(W + (size_t)(kb + br) * 256 + bc);
        }
        __syncthreads();
        #pragma unroll
        for (int k = 0; k < 16; k++) {
            // broadcast A pairs: 4x ld.shared.v2.b64 (all lanes same addr)
            ulonglong2 a01 = *(const ulonglong2*)&As[k][ty * 8 + 0];
            ulonglong2 a23 = *(const ulonglong2*)&As[k][ty * 8 + 2];
            ulonglong2 a45 = *(const ulonglong2*)&As[k][ty * 8 + 4];
            ulonglong2 a67 = *(const ulonglong2*)&As[k][ty * 8 + 6];
            // B pairs: LDS.128 -> two aligned b64 pairs each (conflict-free)
            ulonglong2 b01 = *(const ulonglong2*)&Bs[k][tx * 4];
            ulonglong2 b23 = *(const ulonglong2*)&Bs[k][128 + tx * 4];
            unsigned long long pa[8];
            pa[0] = a01.x; pa[1] = a01.y; pa[2] = a23.x; pa[3] = a23.y;
            pa[4] = a45.x; pa[5] = a45.y; pa[6] = a67.x; pa[7] = a67.y;
            #pragma unroll
            for (int i = 0; i < 8; i++) {
                FMA2(acc2[i][0], pa[i], b01.x);
                FMA2(acc2[i][1], pa[i], b01.y);
                FMA2(acc2[i][2], pa[i], b23.x);
                FMA2(acc2[i][3], pa[i], b23.y);
            }
        }
        __syncthreads();
    }

    float bv[8];
    #pragma unroll
    for (int j = 0; j < 4; j++) {
        bv[j]     = bias[tx * 4 + j];
        bv[4 + j] = bias[128 + tx * 4 + j];
    }

    #pragma unroll
    for (int i = 0; i < 8; i++) {
        int row = GATHER ? ridx[ty * 8 + i] : (mBase + ty * 8 + i);
        if (GATHER && row < 0) continue;
        float c0, c1, c2, c3, c4, c5, c6, c7;
        UNPACK2(c0, c1, acc2[i][0]);
        UNPACK2(c2, c3, acc2[i][1]);
        UNPACK2(c4, c5, acc2[i][2]);
        UNPACK2(c6, c7, acc2[i][3]);
        float4 o0, o1;
        o0.x = fmaxf(c0 + bv[0], 0.f);
        o0.y = fmaxf(c1 + bv[1], 0.f);
        o0.z = fmaxf(c2 + bv[2], 0.f);
        o0.w = fmaxf(c3 + bv[3], 0.f);
        o1.x = fmaxf(c4 + bv[4], 0.f);
        o1.y = fmaxf(c5 + bv[5], 0.f);
        o1.z = fmaxf(c6 + bv[6], 0.f);
        o1.w = fmaxf(c7 + bv[7], 0.f);
        float* op = Out + (size_t)row * 256;
        *(float4*)(op + tx * 4)       = o0;
        *(float4*)(op + 128 + tx * 4) = o1;
    }
}

// ---------------------------------------------------------------------------
// Head + routing: warp per sample-group. logits = h@W2+b2, softmax, tau mask,
// argmax, compaction of routed samples into per-expert lists.
// ---------------------------------------------------------------------------
__global__ __launch_bounds__(256)
void head_route(const float* __restrict__ Hbuf,
                const float* __restrict__ W2, const float* __restrict__ b2,
                const float* __restrict__ tau,
                float* __restrict__ outLogits, float* __restrict__ outDepth)
{
    __shared__ float Wst[8][256];
    __shared__ float b2s[8], taus[8];
    const int tid = threadIdx.x;
    for (int i = tid; i < 2048; i += 256) Wst[i & 7][i >> 3] = W2[i];
    if (tid < 8) { b2s[tid] = b2[tid]; taus[tid] = tau[tid]; }
    __syncthreads();

    const int wid = tid >> 5, lane = tid & 31;
    const int s0 = (blockIdx.x * 8 + wid) * 16;

    for (int grp = 0; grp < 4; grp++) {
        const int sbase = s0 + grp * 4;
        float a0[8], a1[8], a2[8], a3[8];
        #pragma unroll
        for (int j = 0; j < 8; j++) a0[j] = a1[j] = a2[j] = a3[j] = 0.f;
        #pragma unroll
        for (int t = 0; t < 8; t++) {
            int col = t * 32 + lane;
            float w[8];
            #pragma unroll
            for (int j = 0; j < 8; j++) w[j] = Wst[j][col];
            float h0 = Hbuf[(size_t)(sbase + 0) * 256 + col];
            float h1 = Hbuf[(size_t)(sbase + 1) * 256 + col];
            float h2 = Hbuf[(size_t)(sbase + 2) * 256 + col];
            float h3 = Hbuf[(size_t)(sbase + 3) * 256 + col];
            #pragma unroll
            for (int j = 0; j < 8; j++) {
                a0[j] += h0 * w[j]; a1[j] += h1 * w[j];
                a2[j] += h2 * w[j]; a3[j] += h3 * w[j];
            }
        }
        #pragma unroll
        for (int j = 0; j < 8; j++) {
            #pragma unroll
            for (int off = 16; off; off >>= 1) {
                a0[j] += __shfl_xor_sync(0xffffffffu, a0[j], off);
                a1[j] += __shfl_xor_sync(0xffffffffu, a1[j], off);
                a2[j] += __shfl_xor_sync(0xffffffffu, a2[j], off);
                a3[j] += __shfl_xor_sync(0xffffffffu, a3[j], off);
            }
        }
        if (lane < 4) {
            int s = sbase + lane;
            float lg[8];
            float mx = -1e30f;
            #pragma unroll
            for (int j = 0; j < 8; j++) {
                float v = (lane == 0) ? a0[j] : (lane == 1) ? a1[j] : (lane == 2) ? a2[j] : a3[j];
                lg[j] = v + b2s[j];
                mx = fmaxf(mx, lg[j]);
            }
            float e[8], ss = 0.f;
            #pragma unroll
            for (int j = 0; j < 8; j++) { e[j] = expf(lg[j] - mx); ss += e[j]; }
            float inv = 1.0f / ss;
            int best = -1; float bp = -1.f;
            #pragma unroll
            for (int j = 0; j < 8; j++) {
                float pj = e[j] * inv;
                if (pj >= taus[j] && pj > bp) { bp = pj; best = j; }
            }
            float* lo = outLogits + (size_t)s * 8;
            #pragma unroll
            for (int j = 0; j < 8; j++) lo[j] = lg[j];
            outDepth[s] = (best >= 0) ? 1.0f : 0.0f;
            if (best >= 0) {
                int pos = atomicAdd(&g_cnt[best], 1);
                g_idx[best * Bn + pos] = s;
            }
        }
    }
}

// ---------------------------------------------------------------------------
// Expert head over compacted lists.
// ---------------------------------------------------------------------------
__global__ __launch_bounds__(256)
void expert_head(const float* __restrict__ Hbuf,
                 const float* __restrict__ Wc2, const float* __restrict__ bc2,
                 float* __restrict__ outLogits)
{
    const int c    = blockIdx.z;
    const int cnt  = g_cnt[c];
    const int base = blockIdx.y * 128;
    if (base >= cnt) return;

    __shared__ float Wst[8][256];
    __shared__ float bcs[8];
    const int tid = threadIdx.x;
    const float* W = Wc2 + (size_t)c * 2048;
    for (int i = tid; i < 2048; i += 256) Wst[i & 7][i >> 3] = W[i];
    if (tid < 8) bcs[tid] = bc2[c * 8 + tid];
    __syncthreads();

    const int wid = tid >> 5, lane = tid & 31;

    for (int grp = 0; grp < 4; grp++) {
        const int gib = base + wid * 16 + grp * 4;
        int s_0 = (gib + 0 < cnt) ? g_idx[c * Bn + gib + 0] : -1;
        int s_1 = (gib + 1 < cnt) ? g_idx[c * Bn + gib + 1] : -1;
        int s_2 = (gib + 2 < cnt) ? g_idx[c * Bn + gib + 2] : -1;
        int s_3 = (gib + 3 < cnt) ? g_idx[c * Bn + gib + 3] : -1;
        if (s_0 < 0) continue;

        float a0[8], a1[8], a2[8], a3[8];
        #pragma unroll
        for (int j = 0; j < 8; j++) a0[j] = a1[j] = a2[j] = a3[j] = 0.f;
        #pragma unroll
        for (int t = 0; t < 8; t++) {
            int col = t * 32 + lane;
            float w[8];
            #pragma unroll
            for (int j = 0; j < 8; j++) w[j] = Wst[j][col];
            float h0 = Hbuf[(size_t)s_0 * 256 + col];
            float h1 = (s_1 >= 0) ? Hbuf[(size_t)s_1 * 256 + col] : 0.f;
            float h2 = (s_2 >= 0) ? Hbuf[(size_t)s_2 * 256 + col] : 0.f;
            float h3 = (s_3 >= 0) ? Hbuf[(size_t)s_3 * 256 + col] : 0.f;
            #pragma unroll
            for (int j = 0; j < 8; j++) {
                a0[j] += h0 * w[j]; a1[j] += h1 * w[j];
                a2[j] += h2 * w[j]; a3[j] += h3 * w[j];
            }
        }
        #pragma unroll
        for (int j = 0; j < 8; j++) {
            #pragma unroll
            for (int off = 16; off; off >>= 1) {
                a0[j] += __shfl_xor_sync(0xffffffffu, a0[j], off);
                a1[j] += __shfl_xor_sync(0xffffffffu, a1[j], off);
                a2[j] += __shfl_xor_sync(0xffffffffu, a2[j], off);
                a3[j] += __shfl_xor_sync(0xffffffffu, a3[j], off);
            }
        }
        if (lane < 4) {
            int s = (lane == 0) ? s_0 : (lane == 1) ? s_1 : (lane == 2) ? s_2 : s_3;
            if (s >= 0) {
                float* lo = outLogits + (size_t)s * 8;
                #pragma unroll
                for (int j = 0; j < 8; j++) {
                    float v = (lane == 0) ? a0[j] : (lane == 1) ? a1[j] : (lane == 2) ? a2[j] : a3[j];
                    lo[j] = v + bcs[j];
                }
            }
        }
    }
}

// ---------------------------------------------------------------------------
extern "C" void kernel_launch(void* const* d_in, const int* in_sizes, int n_in,
                              void* d_out, int out_size)
{
    const float* x   = (const float*)d_in[0];
    const float* W1  = (const float*)d_in[1];
    const float* b1  = (const float*)d_in[2];
    const float* W2  = (const float*)d_in[3];
    const float* b2  = (const float*)d_in[4];
    const float* Wc1 = (const float*)d_in[5];
    const float* bc1 = (const float*)d_in[6];
    const float* Wc2 = (const float*)d_in[7];
    const float* bc2 = (const float*)d_in[8];
    const float* tau = (const float*)d_in[9];

    float* out       = (float*)d_out;
    float* outLogits = out;
    float* outH      = out + (size_t)Bn * Cc;
    float* outDepth  = out + (size_t)Bn * (Cc + Hh);

    zero_cnt_kernel<<<1, 32>>>();

    // Root: h = relu(x @ W1 + b1)
    gemm64x256_relu<false><<<dim3(1, Bn / 64, 1), 256>>>(x, W1, b1, outH);

    // Head logits + softmax + routing + compaction
    head_route<<<Bn / 128, 256>>>(outH, W2, b2, tau, outLogits, outDepth);

    // Expert dense (gathered, in place)
    gemm64x256_relu<true><<<dim3(1, Bn / 64, Cc), 256>>>(outH, Wc1, bc1, outH);

    // Expert head
    expert_head<<<dim3(1, Bn / 128, Cc), 256>>>(outH, Wc2, bc2, outLogits);
}

// round 4
// speedup vs baseline: 1.3284x; 1.3284x over previous
#include <cuda_runtime.h>
#include <math.h>
#include <stdint.h>

#define Bn 131072
#define Dd 256
#define Hh 256
#define Cc 8

// ---------------- scratch (device globals; no allocs allowed) ----------------
__device__ int   g_cnt[Cc];
__device__ int   g_idx[Cc * Bn];
__device__ float g_h[(size_t)Bn * Hh];   // root hidden copy (gather source)

__global__ void zero_cnt_kernel() {
    if (threadIdx.x < Cc) g_cnt[threadIdx.x] = 0;
}

// ---------------- helpers ----------------
__device__ __forceinline__ void tf32_split(float x, float& hi, float& lo) {
    uint32_t h;
    asm("cvt.rna.tf32.f32 %0, %1;" : "=r"(h) : "f"(x));
    float hf = __uint_as_float(h);
    float r = x - hf;
    uint32_t l;
    asm("cvt.rna.tf32.f32 %0, %1;" : "=r"(l) : "f"(r));
    hi = hf; lo = __uint_as_float(l);
}

__device__ __forceinline__ void mma_tf32(float* d, const uint32_t* a, uint32_t b0, uint32_t b1) {
    asm("mma.sync.aligned.m16n8k8.row.col.f32.tf32.tf32.f32 "
        "{%0,%1,%2,%3}, {%4,%5,%6,%7}, {%8,%9}, {%0,%1,%2,%3};"
        : "+f"(d[0]), "+f"(d[1]), "+f"(d[2]), "+f"(d[3])
        : "r"(a[0]), "r"(a[1]), "r"(a[2]), "r"(a[3]), "r"(b0), "r"(b1));
}

// smem layout (floats): Ahi[4][8][32][4]=4096 | Alo | Bhi[4][16][32][2]=4096 | Blo
#define SM_AHI 0
#define SM_ALO 4096
#define SM_BHI 8192
#define SM_BLO 12288
#define SM_FLOATS 16384
#define SMEM_BYTES (SM_FLOATS * 4 + 512)

// ---------------------------------------------------------------------------
// mma.sync 3xTF32 GEMM: Out[128 rows, nBase..nBase+128) = relu(A@W + bias)
// GATHER: rows from per-expert list, A = g_h. Root: dual-store Out and g_h.
// ---------------------------------------------------------------------------
template<bool GATHER>
__global__ __launch_bounds__(256, 2)
void gemm_mma(const float* __restrict__ Ain,
              const float* __restrict__ Wall,
              const float* __restrict__ ball,
              float* __restrict__ Out)
{
    extern __shared__ float sm[];
    int* ridx = (int*)(sm + SM_FLOATS);

    const int tid  = threadIdx.x;
    const int wid  = tid >> 5;
    const int lane = tid & 31;
    const int mBase = blockIdx.y * 128;
    const int nBase = blockIdx.x * 128;

    const float* A;
    const float* W;
    const float* bias;
    if (GATHER) {
        const int c   = blockIdx.z;
        const int cnt = g_cnt[c];
        if (mBase >= cnt) return;
        A    = g_h;
        W    = Wall + (size_t)c * 65536;
        bias = ball + c * 256;
        if (tid < 128) {
            int gi = mBase + tid;
            ridx[tid] = (gi < cnt) ? g_idx[c * Bn + gi] : -1;
        }
        __syncthreads();
    } else {
        A    = Ain;
        W    = Wall;
        bias = ball;
    }

    // A staging mapping: thread -> row ar, k-half ah (16 floats)
    const int ar = tid >> 1;
    const int ah = tid & 1;
    int grow = GATHER ? ridx[ar] : (mBase + ar);
    const bool aok = (!GATHER) || (grow >= 0);
    const float* ap = A + (size_t)(aok ? grow : 0) * 256 + ah * 16;
    const int ag   = ar & 7;
    const int am16 = ar >> 4;
    const int ahi8 = (ar >> 3) & 1;

    // B staging mapping: thread -> k-row bkr, n-seg bn0
    const int bkr = tid >> 3;
    const int bn0 = (tid & 7) * 16;
    const float* bp = W + (size_t)bkr * 256 + nBase + bn0;
    const int bk8 = bkr >> 3;
    const int btg = bkr & 3;
    const int bbh = (bkr >> 2) & 1;

    const int warp_m = wid & 3;    // 4 groups of 32 rows
    const int warp_n = wid >> 2;   // 2 groups of 64 cols

    float acc[2][8][4];
    #pragma unroll
    for (int i = 0; i < 2; i++)
        #pragma unroll
        for (int j = 0; j < 8; j++)
            #pragma unroll
            for (int t = 0; t < 4; t++) acc[i][j][t] = 0.f;

    for (int kb = 0; kb < 8; kb++) {
        // ---- stage A chunk (rows x 32k), tf32-split, fragment order ----
        #pragma unroll
        for (int q = 0; q < 4; q++) {
            float4 v = aok ? *(const float4*)(ap + kb * 32 + q * 4)
                           : make_float4(0.f, 0.f, 0.f, 0.f);
            int k     = ah * 16 + q * 4;
            int k8    = k >> 3;
            int chalf = (k >> 2) & 1;
            int base  = ((k8 * 8 + am16) * 32 + ag * 4) * 4 + (ahi8 + 2 * chalf);
            float h0, l0, h1, l1, h2, l2, h3, l3;
            tf32_split(v.x, h0, l0);
            tf32_split(v.y, h1, l1);
            tf32_split(v.z, h2, l2);
            tf32_split(v.w, h3, l3);
            sm[SM_AHI + base + 0]  = h0;  sm[SM_ALO + base + 0]  = l0;
            sm[SM_AHI + base + 4]  = h1;  sm[SM_ALO + base + 4]  = l1;
            sm[SM_AHI + base + 8]  = h2;  sm[SM_ALO + base + 8]  = l2;
            sm[SM_AHI + base + 12] = h3;  sm[SM_ALO + base + 12] = l3;
        }
        // ---- stage B chunk (32k x 128n), tf32-split, fragment order ----
        #pragma unroll
        for (int q = 0; q < 4; q++) {
            float4 v = *(const float4*)(bp + (size_t)kb * 32 * 256 + q * 4);
            int nn  = bn0 + q * 4;
            int n8  = nn >> 3;
            int g0  = nn & 7;       // 0 or 4
            int base = ((bk8 * 16 + n8) * 32 + g0 * 4 + btg) * 2 + bbh;
            float h0, l0, h1, l1, h2, l2, h3, l3;
            tf32_split(v.x, h0, l0);
            tf32_split(v.y, h1, l1);
            tf32_split(v.z, h2, l2);
            tf32_split(v.w, h3, l3);
            sm[SM_BHI + base + 0]  = h0;  sm[SM_BLO + base + 0]  = l0;
            sm[SM_BHI + base + 8]  = h1;  sm[SM_BLO + base + 8]  = l1;
            sm[SM_BHI + base + 16] = h2;  sm[SM_BLO + base + 16] = l2;
            sm[SM_BHI + base + 24] = h3;  sm[SM_BLO + base + 24] = l3;
        }
        __syncthreads();

        // ---- MMA phase ----
        #pragma unroll
        for (int k8 = 0; k8 < 4; k8++) {
            uint32_t ahf[2][4], alf[2][4];
            #pragma unroll
            for (int i = 0; i < 2; i++) {
                int m16 = warp_m * 2 + i;
                int off = ((k8 * 8 + m16) * 32 + lane) * 4;
                *(uint4*)ahf[i] = *(const uint4*)(sm + SM_AHI + off);
                *(uint4*)alf[i] = *(const uint4*)(sm + SM_ALO + off);
            }
            #pragma unroll
            for (int j = 0; j < 8; j++) {
                int n8  = warp_n * 8 + j;
                int off = ((k8 * 16 + n8) * 32 + lane) * 2;
                float2 bh2 = *(const float2*)(sm + SM_BHI + off);
                float2 bl2 = *(const float2*)(sm + SM_BLO + off);
                uint32_t bh0 = __float_as_uint(bh2.x), bh1 = __float_as_uint(bh2.y);
                uint32_t bl0 = __float_as_uint(bl2.x), bl1 = __float_as_uint(bl2.y);
                #pragma unroll
                for (int i = 0; i < 2; i++) {
                    mma_tf32(acc[i][j], ahf[i], bh0, bh1);
                    mma_tf32(acc[i][j], ahf[i], bl0, bl1);
                    mma_tf32(acc[i][j], alf[i], bh0, bh1);
                }
            }
        }
        __syncthreads();
    }

    // ---- epilogue: bias + relu, store (dual-store for root) ----
    const int g  = lane >> 2;
    const int tg = lane & 3;
    #pragma unroll
    for (int i = 0; i < 2; i++) {
        int rl0 = warp_m * 32 + i * 16 + g;
        int rl1 = rl0 + 8;
        int r0, r1;
        if (GATHER) { r0 = ridx[rl0]; r1 = ridx[rl1]; }
        else        { r0 = mBase + rl0; r1 = mBase + rl1; }
        #pragma unroll
        for (int j = 0; j < 8; j++) {
            int col = nBase + warp_n * 64 + j * 8 + tg * 2;
            float bv0 = __ldg(bias + col);
            float bv1 = __ldg(bias + col + 1);
            float2 v0 = make_float2(fmaxf(acc[i][j][0] + bv0, 0.f),
                                    fmaxf(acc[i][j][1] + bv1, 0.f));
            float2 v1 = make_float2(fmaxf(acc[i][j][2] + bv0, 0.f),
                                    fmaxf(acc[i][j][3] + bv1, 0.f));
            if (!GATHER) {
                *(float2*)(Out + (size_t)r0 * 256 + col) = v0;
                *(float2*)(Out + (size_t)r1 * 256 + col) = v1;
                *(float2*)(g_h + (size_t)r0 * 256 + col) = v0;
                *(float2*)(g_h + (size_t)r1 * 256 + col) = v1;
            } else {
                if (r0 >= 0) *(float2*)(Out + (size_t)r0 * 256 + col) = v0;
                if (r1 >= 0) *(float2*)(Out + (size_t)r1 * 256 + col) = v1;
            }
        }
    }
}

// ---------------------------------------------------------------------------
// Head + routing (4 samples in flight per warp, 16 per warp total).
// ---------------------------------------------------------------------------
__global__ __launch_bounds__(256)
void head_route(const float* __restrict__ Hbuf,
                const float* __restrict__ W2, const float* __restrict__ b2,
                const float* __restrict__ tau,
                float* __restrict__ outLogits, float* __restrict__ outDepth)
{
    __shared__ float Wst[8][256];
    __shared__ float b2s[8], taus[8];
    const int tid = threadIdx.x;
    for (int i = tid; i < 2048; i += 256) Wst[i & 7][i >> 3] = W2[i];
    if (tid < 8) { b2s[tid] = b2[tid]; taus[tid] = tau[tid]; }
    __syncthreads();

    const int wid = tid >> 5, lane = tid & 31;
    const int s0 = (blockIdx.x * 8 + wid) * 16;

    for (int grp = 0; grp < 4; grp++) {
        const int sbase = s0 + grp * 4;
        float a0[8], a1[8], a2[8], a3[8];
        #pragma unroll
        for (int j = 0; j < 8; j++) a0[j] = a1[j] = a2[j] = a3[j] = 0.f;
        #pragma unroll
        for (int t = 0; t < 8; t++) {
            int col = t * 32 + lane;
            float w[8];
            #pragma unroll
            for (int j = 0; j < 8; j++) w[j] = Wst[j][col];
            float h0 = Hbuf[(size_t)(sbase + 0) * 256 + col];
            float h1 = Hbuf[(size_t)(sbase + 1) * 256 + col];
            float h2 = Hbuf[(size_t)(sbase + 2) * 256 + col];
            float h3 = Hbuf[(size_t)(sbase + 3) * 256 + col];
            #pragma unroll
            for (int j = 0; j < 8; j++) {
                a0[j] += h0 * w[j]; a1[j] += h1 * w[j];
                a2[j] += h2 * w[j]; a3[j] += h3 * w[j];
            }
        }
        #pragma unroll
        for (int j = 0; j < 8; j++) {
            #pragma unroll
            for (int off = 16; off; off >>= 1) {
                a0[j] += __shfl_xor_sync(0xffffffffu, a0[j], off);
                a1[j] += __shfl_xor_sync(0xffffffffu, a1[j], off);
                a2[j] += __shfl_xor_sync(0xffffffffu, a2[j], off);
                a3[j] += __shfl_xor_sync(0xffffffffu, a3[j], off);
            }
        }
        if (lane < 4) {
            int s = sbase + lane;
            float lg[8];
            float mx = -1e30f;
            #pragma unroll
            for (int j = 0; j < 8; j++) {
                float v = (lane == 0) ? a0[j] : (lane == 1) ? a1[j] : (lane == 2) ? a2[j] : a3[j];
                lg[j] = v + b2s[j];
                mx = fmaxf(mx, lg[j]);
            }
            float e[8], ss = 0.f;
            #pragma unroll
            for (int j = 0; j < 8; j++) { e[j] = expf(lg[j] - mx); ss += e[j]; }
            float inv = 1.0f / ss;
            int best = -1; float bp = -1.f;
            #pragma unroll
            for (int j = 0; j < 8; j++) {
                float pj = e[j] * inv;
                if (pj >= taus[j] && pj > bp) { bp = pj; best = j; }
            }
            float* lo = outLogits + (size_t)s * 8;
            #pragma unroll
            for (int j = 0; j < 8; j++) lo[j] = lg[j];
            outDepth[s] = (best >= 0) ? 1.0f : 0.0f;
            if (best >= 0) {
                int pos = atomicAdd(&g_cnt[best], 1);
                g_idx[best * Bn + pos] = s;
            }
        }
    }
}

// ---------------------------------------------------------------------------
// Expert head over compacted lists (reads h_c from Out-h region).
// ---------------------------------------------------------------------------
__global__ __launch_bounds__(256)
void expert_head(const float* __restrict__ Hbuf,
                 const float* __restrict__ Wc2, const float* __restrict__ bc2,
                 float* __restrict__ outLogits)
{
    const int c    = blockIdx.z;
    const int cnt  = g_cnt[c];
    const int base = blockIdx.y * 128;
    if (base >= cnt) return;

    __shared__ float Wst[8][256];
    __shared__ float bcs[8];
    const int tid = threadIdx.x;
    const float* W = Wc2 + (size_t)c * 2048;
    for (int i = tid; i < 2048; i += 256) Wst[i & 7][i >> 3] = W[i];
    if (tid < 8) bcs[tid] = bc2[c * 8 + tid];
    __syncthreads();

    const int wid = tid >> 5, lane = tid & 31;

    for (int grp = 0; grp < 4; grp++) {
        const int gib = base + wid * 16 + grp * 4;
        int s_0 = (gib + 0 < cnt) ? g_idx[c * Bn + gib + 0] : -1;
        int s_1 = (gib + 1 < cnt) ? g_idx[c * Bn + gib + 1] : -1;
        int s_2 = (gib + 2 < cnt) ? g_idx[c * Bn + gib + 2] : -1;
        int s_3 = (gib + 3 < cnt) ? g_idx[c * Bn + gib + 3] : -1;
        if (s_0 < 0) continue;

        float a0[8], a1[8], a2[8], a3[8];
        #pragma unroll
        for (int j = 0; j < 8; j++) a0[j] = a1[j] = a2[j] = a3[j] = 0.f;
        #pragma unroll
        for (int t = 0; t < 8; t++) {
            int col = t * 32 + lane;
            float w[8];
            #pragma unroll
            for (int j = 0; j < 8; j++) w[j] = Wst[j][col];
            float h0 = Hbuf[(size_t)s_0 * 256 + col];
            float h1 = (s_1 >= 0) ? Hbuf[(size_t)s_1 * 256 + col] : 0.f;
            float h2 = (s_2 >= 0) ? Hbuf[(size_t)s_2 * 256 + col] : 0.f;
            float h3 = (s_3 >= 0) ? Hbuf[(size_t)s_3 * 256 + col] : 0.f;
            #pragma unroll
            for (int j = 0; j < 8; j++) {
                a0[j] += h0 * w[j]; a1[j] += h1 * w[j];
                a2[j] += h2 * w[j]; a3[j] += h3 * w[j];
            }
        }
        #pragma unroll
        for (int j = 0; j < 8; j++) {
            #pragma unroll
            for (int off = 16; off; off >>= 1) {
                a0[j] += __shfl_xor_sync(0xffffffffu, a0[j], off);
                a1[j] += __shfl_xor_sync(0xffffffffu, a1[j], off);
                a2[j] += __shfl_xor_sync(0xffffffffu, a2[j], off);
                a3[j] += __shfl_xor_sync(0xffffffffu, a3[j], off);
            }
        }
        if (lane < 4) {
            int s = (lane == 0) ? s_0 : (lane == 1) ? s_1 : (lane == 2) ? s_2 : s_3;
            if (s >= 0) {
                float* lo = outLogits + (size_t)s * 8;
                #pragma unroll
                for (int j = 0; j < 8; j++) {
                    float v = (lane == 0) ? a0[j] : (lane == 1) ? a1[j] : (lane == 2) ? a2[j] : a3[j];
                    lo[j] = v + bcs[j];
                }
            }
        }
    }
}

// ---------------------------------------------------------------------------
extern "C" void kernel_launch(void* const* d_in, const int* in_sizes, int n_in,
                              void* d_out, int out_size)
{
    const float* x   = (const float*)d_in[0];
    const float* W1  = (const float*)d_in[1];
    const float* b1  = (const float*)d_in[2];
    const float* W2  = (const float*)d_in[3];
    const float* b2  = (const float*)d_in[4];
    const float* Wc1 = (const float*)d_in[5];
    const float* bc1 = (const float*)d_in[6];
    const float* Wc2 = (const float*)d_in[7];
    const float* bc2 = (const float*)d_in[8];
    const float* tau = (const float*)d_in[9];

    float* out       = (float*)d_out;
    float* outLogits = out;
    float* outH      = out + (size_t)Bn * Cc;
    float* outDepth  = out + (size_t)Bn * (Cc + Hh);

    static bool attr_done = false;
    if (!attr_done) {
        cudaFuncSetAttribute(gemm_mma<false>, cudaFuncAttributeMaxDynamicSharedMemorySize, SMEM_BYTES);
        cudaFuncSetAttribute(gemm_mma<true>,  cudaFuncAttributeMaxDynamicSharedMemorySize, SMEM_BYTES);
        attr_done = true;
    }

    zero_cnt_kernel<<<1, 32>>>();

    // Root: h = relu(x @ W1 + b1) -> outH and g_h (dual store)
    gemm_mma<false><<<dim3(2, Bn / 128, 1), 256, SMEM_BYTES>>>(x, W1, b1, outH);

    // Head logits + softmax + routing + compaction
    head_route<<<Bn / 128, 256>>>(outH, W2, b2, tau, outLogits, outDepth);

    // Expert dense: gather from g_h, write routed rows of outH
    gemm_mma<true><<<dim3(2, Bn / 128, Cc), 256, SMEM_BYTES>>>(nullptr, Wc1, bc1, outH);

    // Expert head: overwrite logits for routed rows
    expert_head<<<dim3(1, Bn / 128, Cc), 256>>>(outH, Wc2, bc2, outLogits);
}

// round 5
// speedup vs baseline: 1.6072x; 1.2099x over previous
#include <cuda_runtime.h>
#include <math.h>
#include <stdint.h>

#define Bn 131072
#define Dd 256
#define Hh 256
#define Cc 8

// ---------------- scratch (device globals; no allocs allowed) ----------------
__device__ int    g_cnt[Cc];
__device__ int    g_idx[Cc * Bn];
__device__ float  g_h[(size_t)Bn * Hh];          // root hidden copy (gather source)
__device__ float4 g_wfrag[9 * 32768];            // [mat][k8g*32+n8][lane] = {bh0,bh1,bl0,bl1}

__global__ void zero_cnt_kernel() {
    if (threadIdx.x < Cc) g_cnt[threadIdx.x] = 0;
}

// ---------------- helpers ----------------
__device__ __forceinline__ void tf32_split(float x, float& hi, float& lo) {
    uint32_t h;
    asm("cvt.rna.tf32.f32 %0, %1;" : "=r"(h) : "f"(x));
    float hf = __uint_as_float(h);
    float r = x - hf;
    uint32_t l;
    asm("cvt.rna.tf32.f32 %0, %1;" : "=r"(l) : "f"(r));
    hi = hf; lo = __uint_as_float(l);
}

__device__ __forceinline__ void mma_tf32(float* d, const uint32_t* a, uint32_t b0, uint32_t b1) {
    asm("mma.sync.aligned.m16n8k8.row.col.f32.tf32.tf32.f32 "
        "{%0,%1,%2,%3}, {%4,%5,%6,%7}, {%8,%9}, {%0,%1,%2,%3};"
        : "+f"(d[0]), "+f"(d[1]), "+f"(d[2]), "+f"(d[3])
        : "r"(a[0]), "r"(a[1]), "r"(a[2]), "r"(a[3]), "r"(b0), "r"(b1));
}

// ---------------------------------------------------------------------------
// One-time W fragment split: mat 0 = W1, mats 1..8 = Wc1 experts.
// frag[lane] = {hi(W[k][n]), hi(W[k+4][n]), lo(W[k][n]), lo(W[k+4][n])}
// with k = k8g*8 + lane%4, n = n8*8 + lane/4.
// ---------------------------------------------------------------------------
__global__ __launch_bounds__(256)
void split_wfrag(const float* __restrict__ W1, const float* __restrict__ Wc1) {
    int t = blockIdx.x * 256 + threadIdx.x;       // 9 * 32768 total
    int mat  = t >> 15;
    int r    = t & 32767;
    int lane = r & 31;
    int n8   = (r >> 5) & 31;
    int k8g  = r >> 10;
    const float* W = (mat == 0) ? W1 : (Wc1 + (size_t)(mat - 1) * 65536);
    int k = k8g * 8 + (lane & 3);
    int n = n8 * 8 + (lane >> 2);
    float v0 = W[(size_t)k * 256 + n];
    float v1 = W[(size_t)(k + 4) * 256 + n];
    float h0, l0, h1, l1;
    tf32_split(v0, h0, l0);
    tf32_split(v1, h1, l1);
    g_wfrag[t] = make_float4(h0, h1, l0, l1);
}

// smem: two A stages of 8192 floats (Ahi 4096 | Alo 4096), then ridx
#define STG_FLOATS 8192
#define SM_FLOATS  (2 * STG_FLOATS)
#define SMEM_BYTES (SM_FLOATS * 4 + 512)

// ---------------------------------------------------------------------------
// mma.sync 3xTF32 GEMM: Out[128 rows, nBase..nBase+128) = relu(A@W + bias)
// B fragments come straight from g_wfrag (global, cached). A double-buffered.
// ---------------------------------------------------------------------------
template<bool GATHER>
__global__ __launch_bounds__(256, 2)
void gemm_mma(const float* __restrict__ Ain,
              const float* __restrict__ ball,
              float* __restrict__ Out)
{
    extern __shared__ float sm[];
    int* ridx = (int*)(sm + SM_FLOATS);

    const int tid  = threadIdx.x;
    const int wid  = tid >> 5;
    const int lane = tid & 31;
    const int mBase = blockIdx.y * 128;
    const int nBase = blockIdx.x * 128;

    const float* A;
    const float* bias;
    int mat;
    if (GATHER) {
        const int c   = blockIdx.z;
        const int cnt = g_cnt[c];
        if (mBase >= cnt) return;
        A    = g_h;
        bias = ball + c * 256;
        mat  = 1 + c;
        if (tid < 128) {
            int gi = mBase + tid;
            ridx[tid] = (gi < cnt) ? g_idx[c * Bn + gi] : -1;
        }
        __syncthreads();
    } else {
        A    = Ain;
        bias = ball;
        mat  = 0;
    }

    // A staging mapping: thread -> row ar, k-half ah (16 floats)
    const int ar = tid >> 1;
    const int ah = tid & 1;
    int grow = GATHER ? ridx[ar] : (mBase + ar);
    const bool aok = (!GATHER) || (grow >= 0);
    const float* ap = A + (size_t)(aok ? grow : 0) * 256 + ah * 16;
    const int ag   = ar & 7;
    const int am16 = ar >> 4;
    const int ahi8 = (ar >> 3) & 1;

    const int warp_m = wid & 3;    // 4 groups of 32 rows
    const int warp_n = wid >> 2;   // 2 groups of 64 cols

    // B fragment base for this warp: index = (mat*1024 + k8g*32 + n8abs)*32 + lane
    const int n8base = blockIdx.x * 16 + warp_n * 8;
    const float4* __restrict__ bfrag =
        g_wfrag + ((size_t)mat * 1024 + n8base) * 32 + lane;

    float acc[2][8][4];
    #pragma unroll
    for (int i = 0; i < 2; i++)
        #pragma unroll
        for (int j = 0; j < 8; j++)
            #pragma unroll
            for (int t = 0; t < 4; t++) acc[i][j][t] = 0.f;

    // ---- stage A chunk into buffer: split + STS in verified fragment order
    auto stageA = [&](int buf, const float4* v) {
        float* AHI = sm + buf * STG_FLOATS;
        float* ALO = AHI + 4096;
        #pragma unroll
        for (int q = 0; q < 4; q++) {
            int k     = ah * 16 + q * 4;
            int k8    = k >> 3;
            int chalf = (k >> 2) & 1;
            int base  = ((k8 * 8 + am16) * 32 + ag * 4) * 4 + (ahi8 + 2 * chalf);
            float h0, l0, h1, l1, h2, l2, h3, l3;
            tf32_split(v[q].x, h0, l0);
            tf32_split(v[q].y, h1, l1);
            tf32_split(v[q].z, h2, l2);
            tf32_split(v[q].w, h3, l3);
            AHI[base + 0]  = h0;  ALO[base + 0]  = l0;
            AHI[base + 4]  = h1;  ALO[base + 4]  = l1;
            AHI[base + 8]  = h2;  ALO[base + 8]  = l2;
            AHI[base + 12] = h3;  ALO[base + 12] = l3;
        }
    };

    // prologue: chunk 0
    float4 av[4];
    #pragma unroll
    for (int q = 0; q < 4; q++)
        av[q] = aok ? *(const float4*)(ap + q * 4) : make_float4(0.f, 0.f, 0.f, 0.f);
    stageA(0, av);
    __syncthreads();

    for (int kb = 0; kb < 8; kb++) {
        const int p = kb & 1;
        // prefetch next chunk (LDG issues before MMA uses complete)
        float4 nv[4];
        if (kb < 7) {
            #pragma unroll
            for (int q = 0; q < 4; q++)
                nv[q] = aok ? *(const float4*)(ap + (kb + 1) * 32 + q * 4)
                            : make_float4(0.f, 0.f, 0.f, 0.f);
        }

        // ---- MMA phase over buffer p ----
        const float* AHI = sm + p * STG_FLOATS;
        const float* ALO = AHI + 4096;
        #pragma unroll
        for (int k8 = 0; k8 < 4; k8++) {
            uint32_t ahf[2][4], alf[2][4];
            #pragma unroll
            for (int i = 0; i < 2; i++) {
                int m16 = warp_m * 2 + i;
                int off = ((k8 * 8 + m16) * 32 + lane) * 4;
                *(uint4*)ahf[i] = *(const uint4*)(AHI + off);
                *(uint4*)alf[i] = *(const uint4*)(ALO + off);
            }
            const float4* bp = bfrag + (size_t)(kb * 4 + k8) * 1024;  // 32*32
            #pragma unroll
            for (int j = 0; j < 8; j++) {
                float4 bf = __ldg(bp + j * 32);
                uint32_t bh0 = __float_as_uint(bf.x), bh1 = __float_as_uint(bf.y);
                uint32_t bl0 = __float_as_uint(bf.z), bl1 = __float_as_uint(bf.w);
                #pragma unroll
                for (int i = 0; i < 2; i++) {
                    mma_tf32(acc[i][j], ahf[i], bh0, bh1);
                    mma_tf32(acc[i][j], ahf[i], bl0, bl1);
                    mma_tf32(acc[i][j], alf[i], bh0, bh1);
                }
            }
        }

        if (kb < 7) stageA(p ^ 1, nv);
        __syncthreads();
    }

    // ---- epilogue: bias + relu, store (dual-store for root) ----
    const int g  = lane >> 2;
    const int tg = lane & 3;
    #pragma unroll
    for (int i = 0; i < 2; i++) {
        int rl0 = warp_m * 32 + i * 16 + g;
        int rl1 = rl0 + 8;
        int r0, r1;
        if (GATHER) { r0 = ridx[rl0]; r1 = ridx[rl1]; }
        else        { r0 = mBase + rl0; r1 = mBase + rl1; }
        #pragma unroll
        for (int j = 0; j < 8; j++) {
            int col = nBase + warp_n * 64 + j * 8 + tg * 2;
            float bv0 = __ldg(bias + col);
            float bv1 = __ldg(bias + col + 1);
            float2 v0 = make_float2(fmaxf(acc[i][j][0] + bv0, 0.f),
                                    fmaxf(acc[i][j][1] + bv1, 0.f));
            float2 v1 = make_float2(fmaxf(acc[i][j][2] + bv0, 0.f),
                                    fmaxf(acc[i][j][3] + bv1, 0.f));
            if (!GATHER) {
                *(float2*)(Out + (size_t)r0 * 256 + col) = v0;
                *(float2*)(Out + (size_t)r1 * 256 + col) = v1;
                *(float2*)(g_h + (size_t)r0 * 256 + col) = v0;
                *(float2*)(g_h + (size_t)r1 * 256 + col) = v1;
            } else {
                if (r0 >= 0) *(float2*)(Out + (size_t)r0 * 256 + col) = v0;
                if (r1 >= 0) *(float2*)(Out + (size_t)r1 * 256 + col) = v1;
            }
        }
    }
}

// ---------------------------------------------------------------------------
// Head + routing (16 samples per warp).
// ---------------------------------------------------------------------------
__global__ __launch_bounds__(256)
void head_route(const float* __restrict__ Hbuf,
                const float* __restrict__ W2, const float* __restrict__ b2,
                const float* __restrict__ tau,
                float* __restrict__ outLogits, float* __restrict__ outDepth)
{
    __shared__ float Wst[8][256];
    __shared__ float b2s[8], taus[8];
    const int tid = threadIdx.x;
    for (int i = tid; i < 2048; i += 256) Wst[i & 7][i >> 3] = W2[i];
    if (tid < 8) { b2s[tid] = b2[tid]; taus[tid] = tau[tid]; }
    __syncthreads();

    const int wid = tid >> 5, lane = tid & 31;
    const int s0 = (blockIdx.x * 8 + wid) * 16;

    for (int grp = 0; grp < 4; grp++) {
        const int sbase = s0 + grp * 4;
        float a0[8], a1[8], a2[8], a3[8];
        #pragma unroll
        for (int j = 0; j < 8; j++) a0[j] = a1[j] = a2[j] = a3[j] = 0.f;
        #pragma unroll
        for (int t = 0; t < 8; t++) {
            int col = t * 32 + lane;
            float w[8];
            #pragma unroll
            for (int j = 0; j < 8; j++) w[j] = Wst[j][col];
            float h0 = Hbuf[(size_t)(sbase + 0) * 256 + col];
            float h1 = Hbuf[(size_t)(sbase + 1) * 256 + col];
            float h2 = Hbuf[(size_t)(sbase + 2) * 256 + col];
            float h3 = Hbuf[(size_t)(sbase + 3) * 256 + col];
            #pragma unroll
            for (int j = 0; j < 8; j++) {
                a0[j] += h0 * w[j]; a1[j] += h1 * w[j];
                a2[j] += h2 * w[j]; a3[j] += h3 * w[j];
            }
        }
        #pragma unroll
        for (int j = 0; j < 8; j++) {
            #pragma unroll
            for (int off = 16; off; off >>= 1) {
                a0[j] += __shfl_xor_sync(0xffffffffu, a0[j], off);
                a1[j] += __shfl_xor_sync(0xffffffffu, a1[j], off);
                a2[j] += __shfl_xor_sync(0xffffffffu, a2[j], off);
                a3[j] += __shfl_xor_sync(0xffffffffu, a3[j], off);
            }
        }
        if (lane < 4) {
            int s = sbase + lane;
            float lg[8];
            float mx = -1e30f;
            #pragma unroll
            for (int j = 0; j < 8; j++) {
                float v = (lane == 0) ? a0[j] : (lane == 1) ? a1[j] : (lane == 2) ? a2[j] : a3[j];
                lg[j] = v + b2s[j];
                mx = fmaxf(mx, lg[j]);
            }
            float e[8], ss = 0.f;
            #pragma unroll
            for (int j = 0; j < 8; j++) { e[j] = expf(lg[j] - mx); ss += e[j]; }
            float inv = 1.0f / ss;
            int best = -1; float bp = -1.f;
            #pragma unroll
            for (int j = 0; j < 8; j++) {
                float pj = e[j] * inv;
                if (pj >= taus[j] && pj > bp) { bp = pj; best = j; }
            }
            float* lo = outLogits + (size_t)s * 8;
            #pragma unroll
            for (int j = 0; j < 8; j++) lo[j] = lg[j];
            outDepth[s] = (best >= 0) ? 1.0f : 0.0f;
            if (best >= 0) {
                int pos = atomicAdd(&g_cnt[best], 1);
                g_idx[best * Bn + pos] = s;
            }
        }
    }
}

// ---------------------------------------------------------------------------
// Expert head over compacted lists.
// ---------------------------------------------------------------------------
__global__ __launch_bounds__(256)
void expert_head(const float* __restrict__ Hbuf,
                 const float* __restrict__ Wc2, const float* __restrict__ bc2,
                 float* __restrict__ outLogits)
{
    const int c    = blockIdx.z;
    const int cnt  = g_cnt[c];
    const int base = blockIdx.y * 128;
    if (base >= cnt) return;

    __shared__ float Wst[8][256];
    __shared__ float bcs[8];
    const int tid = threadIdx.x;
    const float* W = Wc2 + (size_t)c * 2048;
    for (int i = tid; i < 2048; i += 256) Wst[i & 7][i >> 3] = W[i];
    if (tid < 8) bcs[tid] = bc2[c * 8 + tid];
    __syncthreads();

    const int wid = tid >> 5, lane = tid & 31;

    for (int grp = 0; grp < 4; grp++) {
        const int gib = base + wid * 16 + grp * 4;
        int s_0 = (gib + 0 < cnt) ? g_idx[c * Bn + gib + 0] : -1;
        int s_1 = (gib + 1 < cnt) ? g_idx[c * Bn + gib + 1] : -1;
        int s_2 = (gib + 2 < cnt) ? g_idx[c * Bn + gib + 2] : -1;
        int s_3 = (gib + 3 < cnt) ? g_idx[c * Bn + gib + 3] : -1;
        if (s_0 < 0) continue;

        float a0[8], a1[8], a2[8], a3[8];
        #pragma unroll
        for (int j = 0; j < 8; j++) a0[j] = a1[j] = a2[j] = a3[j] = 0.f;
        #pragma unroll
        for (int t = 0; t < 8; t++) {
            int col = t * 32 + lane;
            float w[8];
            #pragma unroll
            for (int j = 0; j < 8; j++) w[j] = Wst[j][col];
            float h0 = Hbuf[(size_t)s_0 * 256 + col];
            float h1 = (s_1 >= 0) ? Hbuf[(size_t)s_1 * 256 + col] : 0.f;
            float h2 = (s_2 >= 0) ? Hbuf[(size_t)s_2 * 256 + col] : 0.f;
            float h3 = (s_3 >= 0) ? Hbuf[(size_t)s_3 * 256 + col] : 0.f;
            #pragma unroll
            for (int j = 0; j < 8; j++) {
                a0[j] += h0 * w[j]; a1[j] += h1 * w[j];
                a2[j] += h2 * w[j]; a3[j] += h3 * w[j];
            }
        }
        #pragma unroll
        for (int j = 0; j < 8; j++) {
            #pragma unroll
            for (int off = 16; off; off >>= 1) {
                a0[j] += __shfl_xor_sync(0xffffffffu, a0[j], off);
                a1[j] += __shfl_xor_sync(0xffffffffu, a1[j], off);
                a2[j] += __shfl_xor_sync(0xffffffffu, a2[j], off);
                a3[j] += __shfl_xor_sync(0xffffffffu, a3[j], off);
            }
        }
        if (lane < 4) {
            int s = (lane == 0) ? s_0 : (lane == 1) ? s_1 : (lane == 2) ? s_2 : s_3;
            if (s >= 0) {
                float* lo = outLogits + (size_t)s * 8;
                #pragma unroll
                for (int j = 0; j < 8; j++) {
                    float v = (lane == 0) ? a0[j] : (lane == 1) ? a1[j] : (lane == 2) ? a2[j] : a3[j];
                    lo[j] = v + bcs[j];
                }
            }
        }
    }
}

// ---------------------------------------------------------------------------
extern "C" void kernel_launch(void* const* d_in, const int* in_sizes, int n_in,
                              void* d_out, int out_size)
{
    const float* x   = (const float*)d_in[0];
    const float* W1  = (const float*)d_in[1];
    const float* b1  = (const float*)d_in[2];
    const float* W2  = (const float*)d_in[3];
    const float* b2  = (const float*)d_in[4];
    const float* Wc1 = (const float*)d_in[5];
    const float* bc1 = (const float*)d_in[6];
    const float* Wc2 = (const float*)d_in[7];
    const float* bc2 = (const float*)d_in[8];
    const float* tau = (const float*)d_in[9];

    float* out       = (float*)d_out;
    float* outLogits = out;
    float* outH      = out + (size_t)Bn * Cc;
    float* outDepth  = out + (size_t)Bn * (Cc + Hh);

    static bool attr_done = false;
    if (!attr_done) {
        cudaFuncSetAttribute(gemm_mma<false>, cudaFuncAttributeMaxDynamicSharedMemorySize, SMEM_BYTES);
        cudaFuncSetAttribute(gemm_mma<true>,  cudaFuncAttributeMaxDynamicSharedMemorySize, SMEM_BYTES);
        attr_done = true;
    }

    zero_cnt_kernel<<<1, 32>>>();

    // One-time W fragment split (W1 + 8 experts)
    split_wfrag<<<(9 * 32768) / 256, 256>>>(W1, Wc1);

    // Root: h = relu(x @ W1 + b1) -> outH and g_h (dual store)
    gemm_mma<false><<<dim3(2, Bn / 128, 1), 256, SMEM_BYTES>>>(x, b1, outH);

    // Head logits + softmax + routing + compaction
    head_route<<<Bn / 128, 256>>>(outH, W2, b2, tau, outLogits, outDepth);

    // Expert dense: gather from g_h, write routed rows of outH
    gemm_mma<true><<<dim3(2, Bn / 128, Cc), 256, SMEM_BYTES>>>(nullptr, bc1, outH);

    // Expert head: overwrite logits for routed rows
    expert_head<<<dim3(1, Bn / 128, Cc), 256>>>(outH, Wc2, bc2, outLogits);
}

// round 6
// speedup vs baseline: 1.8677x; 1.1620x over previous
#include <cuda_runtime.h>
#include <math.h>
#include <stdint.h>

#define Bn 131072
#define Dd 256
#define Hh 256
#define Cc 8

// ---------------- scratch (device globals; no allocs allowed) ----------------
__device__ int    g_cnt[Cc];
__device__ int    g_idx[Cc * Bn];
__device__ float  g_h[(size_t)Bn * Hh];          // root hidden copy (gather source)
__device__ float4 g_wfrag[9 * 32768];            // [mat][k8g*32+n8][lane] = {bh0,bh1,bl0,bl1}

__global__ void zero_cnt_kernel() {
    if (threadIdx.x < Cc) g_cnt[threadIdx.x] = 0;
}

// ---------------- helpers ----------------
__device__ __forceinline__ void tf32_split(float x, float& hi, float& lo) {
    uint32_t h;
    asm("cvt.rna.tf32.f32 %0, %1;" : "=r"(h) : "f"(x));
    float hf = __uint_as_float(h);
    float r = x - hf;
    uint32_t l;
    asm("cvt.rna.tf32.f32 %0, %1;" : "=r"(l) : "f"(r));
    hi = hf; lo = __uint_as_float(l);
}

__device__ __forceinline__ void mma_tf32(float* d, const uint32_t* a, uint32_t b0, uint32_t b1) {
    asm("mma.sync.aligned.m16n8k8.row.col.f32.tf32.tf32.f32 "
        "{%0,%1,%2,%3}, {%4,%5,%6,%7}, {%8,%9}, {%0,%1,%2,%3};"
        : "+f"(d[0]), "+f"(d[1]), "+f"(d[2]), "+f"(d[3])
        : "r"(a[0]), "r"(a[1]), "r"(a[2]), "r"(a[3]), "r"(b0), "r"(b1));
}

__device__ __forceinline__ uint32_t smem_u32(const void* p) {
    uint32_t a;
    asm("{ .reg .u64 t; cvta.to.shared.u64 t, %1; cvt.u32.u64 %0, t; }" : "=r"(a) : "l"(p));
    return a;
}
#define CP_ASYNC16(dst, src) \
    asm volatile("cp.async.cg.shared.global [%0], [%1], 16;" :: "r"(dst), "l"(src) : "memory")
#define CP_COMMIT()  asm volatile("cp.async.commit_group;" ::: "memory")
#define CP_WAIT0()   asm volatile("cp.async.wait_group 0;" ::: "memory")

// ---------------------------------------------------------------------------
// One-time W fragment split: mat 0 = W1, mats 1..8 = Wc1 experts.
// frag[lane] = {hi(W[k][n]), hi(W[k+4][n]), lo(W[k][n]), lo(W[k+4][n])}
// with k = k8g*8 + lane%4, n = n8*8 + lane/4.
// ---------------------------------------------------------------------------
__global__ __launch_bounds__(256)
void split_wfrag(const float* __restrict__ W1, const float* __restrict__ Wc1) {
    int t = blockIdx.x * 256 + threadIdx.x;       // 9 * 32768 total
    int mat  = t >> 15;
    int r    = t & 32767;
    int lane = r & 31;
    int n8   = (r >> 5) & 31;
    int k8g  = r >> 10;
    const float* W = (mat == 0) ? W1 : (Wc1 + (size_t)(mat - 1) * 65536);
    int k = k8g * 8 + (lane & 3);
    int n = n8 * 8 + (lane >> 2);
    float v0 = W[(size_t)k * 256 + n];
    float v1 = W[(size_t)(k + 4) * 256 + n];
    float h0, l0, h1, l1;
    tf32_split(v0, h0, l0);
    tf32_split(v1, h1, l1);
    g_wfrag[t] = make_float4(h0, h1, l0, l1);
}

// smem (floats): A stages 2x4096 (Ahi 2048 | Alo 2048 each), B stages 2x4096
#define A_STG    4096
#define SM_B0    (2 * A_STG)          /* 8192 */
#define B_STG    4096
#define SM_FLOATS (2 * A_STG + 2 * B_STG)   /* 16384 */
#define SMEM_BYTES (SM_FLOATS * 4 + 512)

// ---------------------------------------------------------------------------
// mma.sync 3xTF32 GEMM: Out[128 rows, nBase..nBase+128) = relu(A@W + bias)
// KC=16; B fragments cp.async-staged into smem; A reg-prefetch + STS; both
// double-buffered; one sync per chunk.
// ---------------------------------------------------------------------------
template<bool GATHER>
__global__ __launch_bounds__(256, 2)
void gemm_mma(const float* __restrict__ Ain,
              const float* __restrict__ ball,
              float* __restrict__ Out)
{
    extern __shared__ float sm[];
    int* ridx = (int*)(sm + SM_FLOATS);

    const int tid  = threadIdx.x;
    const int wid  = tid >> 5;
    const int lane = tid & 31;
    const int mBase = blockIdx.y * 128;
    const int nBase = blockIdx.x * 128;

    const float* A;
    const float* bias;
    int mat;
    if (GATHER) {
        const int c   = blockIdx.z;
        const int cnt = g_cnt[c];
        if (mBase >= cnt) return;
        A    = g_h;
        bias = ball + c * 256;
        mat  = 1 + c;
        if (tid < 128) {
            int gi = mBase + tid;
            ridx[tid] = (gi < cnt) ? g_idx[c * Bn + gi] : -1;
        }
        __syncthreads();
    } else {
        A    = Ain;
        bias = ball;
        mat  = 0;
    }

    // ---- A staging mapping: thread -> row ar, k-half ah (8 floats / chunk)
    const int ar = tid >> 1;
    const int ah = tid & 1;                 // k8 within chunk
    int grow = GATHER ? ridx[ar] : (mBase + ar);
    const bool aok = (!GATHER) || (grow >= 0);
    const float* ap = A + (size_t)(aok ? grow : 0) * 256 + ah * 8;
    const int ag   = ar & 7;
    const int am16 = ar >> 4;
    const int ahi8 = (ar >> 3) & 1;

    // ---- B cp.async mapping: thread copies 4 float4s per chunk
    // dst float4 index t = tid + i*256 ; src frag = (mat*1024 + (kb*2+k8l)*32 + bx16+n8l)*32+lane
    const int bx16 = blockIdx.x * 16;
    const uint32_t smb = smem_u32(sm);

    const int warp_m = wid & 3;    // 4 groups of 32 rows
    const int warp_n = wid >> 2;   // 2 groups of 64 cols

    float acc[2][8][4];
    #pragma unroll
    for (int i = 0; i < 2; i++)
        #pragma unroll
        for (int j = 0; j < 8; j++)
            #pragma unroll
            for (int t = 0; t < 4; t++) acc[i][j][t] = 0.f;

    // ---- stage A chunk (regs -> smem frag order) into buffer
    auto stageA = [&](int buf, const float4* v) {
        float* AHI = sm + buf * A_STG;
        float* ALO = AHI + 2048;
        #pragma unroll
        for (int q = 0; q < 2; q++) {
            int base = ((ah * 8 + am16) * 32 + ag * 4) * 4 + (ahi8 + 2 * q);
            float h0, l0, h1, l1, h2, l2, h3, l3;
            tf32_split(v[q].x, h0, l0);
            tf32_split(v[q].y, h1, l1);
            tf32_split(v[q].z, h2, l2);
            tf32_split(v[q].w, h3, l3);
            AHI[base + 0]  = h0;  ALO[base + 0]  = l0;
            AHI[base + 4]  = h1;  ALO[base + 4]  = l1;
            AHI[base + 8]  = h2;  ALO[base + 8]  = l2;
            AHI[base + 12] = h3;  ALO[base + 12] = l3;
        }
    };
    // ---- issue cp.async for B chunk kb into buffer
    auto stageB = [&](int buf, int kb) {
        uint32_t dbase = smb + (SM_B0 + buf * B_STG) * 4;
        #pragma unroll
        for (int i = 0; i < 4; i++) {
            int t    = tid + i * 256;
            int ln   = t & 31;
            int n8l  = (t >> 5) & 15;
            int k8l  = t >> 9;
            const float4* src = g_wfrag +
                ((size_t)mat * 1024 + (size_t)(kb * 2 + k8l) * 32 + bx16 + n8l) * 32 + ln;
            CP_ASYNC16(dbase + (uint32_t)t * 16, (const void*)src);
        }
        CP_COMMIT();
    };

    // prologue: chunk 0
    {
        float4 av[2];
        #pragma unroll
        for (int q = 0; q < 2; q++)
            av[q] = aok ? *(const float4*)(ap + q * 4) : make_float4(0.f, 0.f, 0.f, 0.f);
        stageA(0, av);
        stageB(0, 0);
        CP_WAIT0();
        __syncthreads();
    }

    for (int kb = 0; kb < 16; kb++) {
        const int p = kb & 1;
        float4 nv[2];
        if (kb < 15) {
            stageB(p ^ 1, kb + 1);     // async, overlaps MMA below
            #pragma unroll
            for (int q = 0; q < 2; q++)
                nv[q] = aok ? *(const float4*)(ap + (kb + 1) * 16 + q * 4)
                            : make_float4(0.f, 0.f, 0.f, 0.f);
        }

        // ---- MMA phase on buffers p ----
        const float* AHI = sm + p * A_STG;
        const float* ALO = AHI + 2048;
        const float* BST = sm + SM_B0 + p * B_STG;
        #pragma unroll
        for (int k8 = 0; k8 < 2; k8++) {
            uint32_t ahf[2][4], alf[2][4];
            #pragma unroll
            for (int i = 0; i < 2; i++) {
                int m16 = warp_m * 2 + i;
                int off = ((k8 * 8 + m16) * 32 + lane) * 4;
                *(uint4*)ahf[i] = *(const uint4*)(AHI + off);
                *(uint4*)alf[i] = *(const uint4*)(ALO + off);
            }
            #pragma unroll
            for (int j = 0; j < 8; j++) {
                int off = ((k8 * 16 + warp_n * 8 + j) * 32 + lane) * 4;
                float4 bf = *(const float4*)(BST + off);
                uint32_t bh0 = __float_as_uint(bf.x), bh1 = __float_as_uint(bf.y);
                uint32_t bl0 = __float_as_uint(bf.z), bl1 = __float_as_uint(bf.w);
                #pragma unroll
                for (int i = 0; i < 2; i++) {
                    mma_tf32(acc[i][j], ahf[i], bh0, bh1);
                    mma_tf32(acc[i][j], ahf[i], bl0, bl1);
                    mma_tf32(acc[i][j], alf[i], bh0, bh1);
                }
            }
        }

        if (kb < 15) {
            stageA(p ^ 1, nv);
            CP_WAIT0();
            __syncthreads();
        }
    }

    // ---- epilogue: bias + relu, store (dual-store for root) ----
    const int g  = lane >> 2;
    const int tg = lane & 3;
    #pragma unroll
    for (int i = 0; i < 2; i++) {
        int rl0 = warp_m * 32 + i * 16 + g;
        int rl1 = rl0 + 8;
        int r0, r1;
        if (GATHER) { r0 = ridx[rl0]; r1 = ridx[rl1]; }
        else        { r0 = mBase + rl0; r1 = mBase + rl1; }
        #pragma unroll
        for (int j = 0; j < 8; j++) {
            int col = nBase + warp_n * 64 + j * 8 + tg * 2;
            float bv0 = __ldg(bias + col);
            float bv1 = __ldg(bias + col + 1);
            float2 v0 = make_float2(fmaxf(acc[i][j][0] + bv0, 0.f),
                                    fmaxf(acc[i][j][1] + bv1, 0.f));
            float2 v1 = make_float2(fmaxf(acc[i][j][2] + bv0, 0.f),
                                    fmaxf(acc[i][j][3] + bv1, 0.f));
            if (!GATHER) {
                *(float2*)(Out + (size_t)r0 * 256 + col) = v0;
                *(float2*)(Out + (size_t)r1 * 256 + col) = v1;
                *(float2*)(g_h + (size_t)r0 * 256 + col) = v0;
                *(float2*)(g_h + (size_t)r1 * 256 + col) = v1;
            } else {
                if (r0 >= 0) *(float2*)(Out + (size_t)r0 * 256 + col) = v0;
                if (r1 >= 0) *(float2*)(Out + (size_t)r1 * 256 + col) = v1;
            }
        }
    }
}

// ---------------------------------------------------------------------------
// Head + routing (16 samples per warp).
// ---------------------------------------------------------------------------
__global__ __launch_bounds__(256)
void head_route(const float* __restrict__ Hbuf,
                const float* __restrict__ W2, const float* __restrict__ b2,
                const float* __restrict__ tau,
                float* __restrict__ outLogits, float* __restrict__ outDepth)
{
    __shared__ float Wst[8][256];
    __shared__ float b2s[8], taus[8];
    const int tid = threadIdx.x;
    for (int i = tid; i < 2048; i += 256) Wst[i & 7][i >> 3] = W2[i];
    if (tid < 8) { b2s[tid] = b2[tid]; taus[tid] = tau[tid]; }
    __syncthreads();

    const int wid = tid >> 5, lane = tid & 31;
    const int s0 = (blockIdx.x * 8 + wid) * 16;

    for (int grp = 0; grp < 4; grp++) {
        const int sbase = s0 + grp * 4;
        float a0[8], a1[8], a2[8], a3[8];
        #pragma unroll
        for (int j = 0; j < 8; j++) a0[j] = a1[j] = a2[j] = a3[j] = 0.f;
        #pragma unroll
        for (int t = 0; t < 8; t++) {
            int col = t * 32 + lane;
            float w[8];
            #pragma unroll
            for (int j = 0; j < 8; j++) w[j] = Wst[j][col];
            float h0 = Hbuf[(size_t)(sbase + 0) * 256 + col];
            float h1 = Hbuf[(size_t)(sbase + 1) * 256 + col];
            float h2 = Hbuf[(size_t)(sbase + 2) * 256 + col];
            float h3 = Hbuf[(size_t)(sbase + 3) * 256 + col];
            #pragma unroll
            for (int j = 0; j < 8; j++) {
                a0[j] += h0 * w[j]; a1[j] += h1 * w[j];
                a2[j] += h2 * w[j]; a3[j] += h3 * w[j];
            }
        }
        #pragma unroll
        for (int j = 0; j < 8; j++) {
            #pragma unroll
            for (int off = 16; off; off >>= 1) {
                a0[j] += __shfl_xor_sync(0xffffffffu, a0[j], off);
                a1[j] += __shfl_xor_sync(0xffffffffu, a1[j], off);
                a2[j] += __shfl_xor_sync(0xffffffffu, a2[j], off);
                a3[j] += __shfl_xor_sync(0xffffffffu, a3[j], off);
            }
        }
        if (lane < 4) {
            int s = sbase + lane;
            float lg[8];
            float mx = -1e30f;
            #pragma unroll
            for (int j = 0; j < 8; j++) {
                float v = (lane == 0) ? a0[j] : (lane == 1) ? a1[j] : (lane == 2) ? a2[j] : a3[j];
                lg[j] = v + b2s[j];
                mx = fmaxf(mx, lg[j]);
            }
            float e[8], ss = 0.f;
            #pragma unroll
            for (int j = 0; j < 8; j++) { e[j] = expf(lg[j] - mx); ss += e[j]; }
            float inv = 1.0f / ss;
            int best = -1; float bp = -1.f;
            #pragma unroll
            for (int j = 0; j < 8; j++) {
                float pj = e[j] * inv;
                if (pj >= taus[j] && pj > bp) { bp = pj; best = j; }
            }
            float* lo = outLogits + (size_t)s * 8;
            #pragma unroll
            for (int j = 0; j < 8; j++) lo[j] = lg[j];
            outDepth[s] = (best >= 0) ? 1.0f : 0.0f;
            if (best >= 0) {
                int pos = atomicAdd(&g_cnt[best], 1);
                g_idx[best * Bn + pos] = s;
            }
        }
    }
}

// ---------------------------------------------------------------------------
// Expert head over compacted lists.
// ---------------------------------------------------------------------------
__global__ __launch_bounds__(256)
void expert_head(const float* __restrict__ Hbuf,
                 const float* __restrict__ Wc2, const float* __restrict__ bc2,
                 float* __restrict__ outLogits)
{
    const int c    = blockIdx.z;
    const int cnt  = g_cnt[c];
    const int base = blockIdx.y * 128;
    if (base >= cnt) return;

    __shared__ float Wst[8][256];
    __shared__ float bcs[8];
    const int tid = threadIdx.x;
    const float* W = Wc2 + (size_t)c * 2048;
    for (int i = tid; i < 2048; i += 256) Wst[i & 7][i >> 3] = W[i];
    if (tid < 8) bcs[tid] = bc2[c * 8 + tid];
    __syncthreads();

    const int wid = tid >> 5, lane = tid & 31;

    for (int grp = 0; grp < 4; grp++) {
        const int gib = base + wid * 16 + grp * 4;
        int s_0 = (gib + 0 < cnt) ? g_idx[c * Bn + gib + 0] : -1;
        int s_1 = (gib + 1 < cnt) ? g_idx[c * Bn + gib + 1] : -1;
        int s_2 = (gib + 2 < cnt) ? g_idx[c * Bn + gib + 2] : -1;
        int s_3 = (gib + 3 < cnt) ? g_idx[c * Bn + gib + 3] : -1;
        if (s_0 < 0) continue;

        float a0[8], a1[8], a2[8], a3[8];
        #pragma unroll
        for (int j = 0; j < 8; j++) a0[j] = a1[j] = a2[j] = a3[j] = 0.f;
        #pragma unroll
        for (int t = 0; t < 8; t++) {
            int col = t * 32 + lane;
            float w[8];
            #pragma unroll
            for (int j = 0; j < 8; j++) w[j] = Wst[j][col];
            float h0 = Hbuf[(size_t)s_0 * 256 + col];
            float h1 = (s_1 >= 0) ? Hbuf[(size_t)s_1 * 256 + col] : 0.f;
            float h2 = (s_2 >= 0) ? Hbuf[(size_t)s_2 * 256 + col] : 0.f;
            float h3 = (s_3 >= 0) ? Hbuf[(size_t)s_3 * 256 + col] : 0.f;
            #pragma unroll
            for (int j = 0; j < 8; j++) {
                a0[j] += h0 * w[j]; a1[j] += h1 * w[j];
                a2[j] += h2 * w[j]; a3[j] += h3 * w[j];
            }
        }
        #pragma unroll
        for (int j = 0; j < 8; j++) {
            #pragma unroll
            for (int off = 16; off; off >>= 1) {
                a0[j] += __shfl_xor_sync(0xffffffffu, a0[j], off);
                a1[j] += __shfl_xor_sync(0xffffffffu, a1[j], off);
                a2[j] += __shfl_xor_sync(0xffffffffu, a2[j], off);
                a3[j] += __shfl_xor_sync(0xffffffffu, a3[j], off);
            }
        }
        if (lane < 4) {
            int s = (lane == 0) ? s_0 : (lane == 1) ? s_1 : (lane == 2) ? s_2 : s_3;
            if (s >= 0) {
                float* lo = outLogits + (size_t)s * 8;
                #pragma unroll
                for (int j = 0; j < 8; j++) {
                    float v = (lane == 0) ? a0[j] : (lane == 1) ? a1[j] : (lane == 2) ? a2[j] : a3[j];
                    lo[j] = v + bcs[j];
                }
            }
        }
    }
}

// ---------------------------------------------------------------------------
extern "C" void kernel_launch(void* const* d_in, const int* in_sizes, int n_in,
                              void* d_out, int out_size)
{
    const float* x   = (const float*)d_in[0];
    const float* W1  = (const float*)d_in[1];
    const float* b1  = (const float*)d_in[2];
    const float* W2  = (const float*)d_in[3];
    const float* b2  = (const float*)d_in[4];
    const float* Wc1 = (const float*)d_in[5];
    const float* bc1 = (const float*)d_in[6];
    const float* Wc2 = (const float*)d_in[7];
    const float* bc2 = (const float*)d_in[8];
    const float* tau = (const float*)d_in[9];

    float* out       = (float*)d_out;
    float* outLogits = out;
    float* outH      = out + (size_t)Bn * Cc;
    float* outDepth  = out + (size_t)Bn * (Cc + Hh);

    static bool attr_done = false;
    if (!attr_done) {
        cudaFuncSetAttribute(gemm_mma<false>, cudaFuncAttributeMaxDynamicSharedMemorySize, SMEM_BYTES);
        cudaFuncSetAttribute(gemm_mma<true>,  cudaFuncAttributeMaxDynamicSharedMemorySize, SMEM_BYTES);
        attr_done = true;
    }

    zero_cnt_kernel<<<1, 32>>>();

    // One-time W fragment split (W1 + 8 experts)
    split_wfrag<<<(9 * 32768) / 256, 256>>>(W1, Wc1);

    // Root: h = relu(x @ W1 + b1) -> outH and g_h (dual store)
    gemm_mma<false><<<dim3(2, Bn / 128, 1), 256, SMEM_BYTES>>>(x, b1, outH);

    // Head logits + softmax + routing + compaction
    head_route<<<Bn / 128, 256>>>(outH, W2, b2, tau, outLogits, outDepth);

    // Expert dense: gather from g_h, write routed rows of outH
    gemm_mma<true><<<dim3(2, Bn / 128, Cc), 256, SMEM_BYTES>>>(nullptr, bc1, outH);

    // Expert head: overwrite logits for routed rows
    expert_head<<<dim3(1, Bn / 128, Cc), 256>>>(outH, Wc2, bc2, outLogits);
}

// round 7
// speedup vs baseline: 1.8688x; 1.0006x over previous
#include <cuda_runtime.h>
#include <math.h>
#include <stdint.h>

#define Bn 131072
#define Dd 256
#define Hh 256
#define Cc 8

// ---------------- scratch (device globals; no allocs allowed) ----------------
__device__ int    g_cnt[Cc];
__device__ int    g_idx[Cc * Bn];
__device__ float  g_h[(size_t)Bn * Hh];          // root hidden copy (gather source)
__device__ float4 g_wfrag[9 * 32768];            // [mat][k8g*32+n8][lane] = {bh0,bh1,bl0,bl1}
__device__ float  g_plog[4][Bn][8];              // partial logits per col-quarter

__global__ void zero_cnt_kernel() {
    if (threadIdx.x < Cc) g_cnt[threadIdx.x] = 0;
}

// ---------------- helpers ----------------
__device__ __forceinline__ void tf32_split(float x, float& hi, float& lo) {
    uint32_t h;
    asm("cvt.rna.tf32.f32 %0, %1;" : "=r"(h) : "f"(x));
    float hf = __uint_as_float(h);
    float r = x - hf;
    uint32_t l;
    asm("cvt.rna.tf32.f32 %0, %1;" : "=r"(l) : "f"(r));
    hi = hf; lo = __uint_as_float(l);
}

__device__ __forceinline__ void mma_tf32(float* d, const uint32_t* a, uint32_t b0, uint32_t b1) {
    asm("mma.sync.aligned.m16n8k8.row.col.f32.tf32.tf32.f32 "
        "{%0,%1,%2,%3}, {%4,%5,%6,%7}, {%8,%9}, {%0,%1,%2,%3};"
        : "+f"(d[0]), "+f"(d[1]), "+f"(d[2]), "+f"(d[3])
        : "r"(a[0]), "r"(a[1]), "r"(a[2]), "r"(a[3]), "r"(b0), "r"(b1));
}

__device__ __forceinline__ uint32_t smem_u32(const void* p) {
    uint32_t a;
    asm("{ .reg .u64 t; cvta.to.shared.u64 t, %1; cvt.u32.u64 %0, t; }" : "=r"(a) : "l"(p));
    return a;
}
#define CP_ASYNC16(dst, src) \
    asm volatile("cp.async.cg.shared.global [%0], [%1], 16;" :: "r"(dst), "l"(src) : "memory")
#define CP_COMMIT()  asm volatile("cp.async.commit_group;" ::: "memory")
#define CP_WAIT0()   asm volatile("cp.async.wait_group 0;" ::: "memory")

// ---------------------------------------------------------------------------
// One-time W fragment split: mat 0 = W1, mats 1..8 = Wc1 experts.
// ---------------------------------------------------------------------------
__global__ __launch_bounds__(256)
void split_wfrag(const float* __restrict__ W1, const float* __restrict__ Wc1) {
    int t = blockIdx.x * 256 + threadIdx.x;       // 9 * 32768 total
    int mat  = t >> 15;
    int r    = t & 32767;
    int lane = r & 31;
    int n8   = (r >> 5) & 31;
    int k8g  = r >> 10;
    const float* W = (mat == 0) ? W1 : (Wc1 + (size_t)(mat - 1) * 65536);
    int k = k8g * 8 + (lane & 3);
    int n = n8 * 8 + (lane >> 2);
    float v0 = W[(size_t)k * 256 + n];
    float v1 = W[(size_t)(k + 4) * 256 + n];
    float h0, l0, h1, l1;
    tf32_split(v0, h0, l0);
    tf32_split(v1, h1, l1);
    g_wfrag[t] = make_float4(h0, h1, l0, l1);
}

// smem (floats): A stages 2x4096 (Ahi 2048 | Alo 2048 each), B stages 2x4096
#define A_STG    4096
#define SM_B0    (2 * A_STG)
#define B_STG    4096
#define SM_FLOATS (2 * A_STG + 2 * B_STG)
#define SMEM_BYTES (SM_FLOATS * 4 + 512)

// ---------------------------------------------------------------------------
// mma.sync 3xTF32 GEMM: Out[128 rows, nBase..nBase+128) = relu(A@W + bias)
// Term-major MMA ordering (RAW chain distance 8). Root fuses partial logits.
// ---------------------------------------------------------------------------
template<bool GATHER>
__global__ __launch_bounds__(256, 2)
void gemm_mma(const float* __restrict__ Ain,
              const float* __restrict__ ball,
              const float* __restrict__ W2,
              float* __restrict__ Out)
{
    extern __shared__ float sm[];
    int* ridx = (int*)(sm + SM_FLOATS);

    const int tid  = threadIdx.x;
    const int wid  = tid >> 5;
    const int lane = tid & 31;
    const int mBase = blockIdx.y * 128;
    const int nBase = blockIdx.x * 128;

    const float* A;
    const float* bias;
    int mat;
    if (GATHER) {
        const int c   = blockIdx.z;
        const int cnt = g_cnt[c];
        if (mBase >= cnt) return;
        A    = g_h;
        bias = ball + c * 256;
        mat  = 1 + c;
        if (tid < 128) {
            int gi = mBase + tid;
            ridx[tid] = (gi < cnt) ? g_idx[c * Bn + gi] : -1;
        }
        __syncthreads();
    } else {
        A    = Ain;
        bias = ball;
        mat  = 0;
    }

    // A staging mapping
    const int ar = tid >> 1;
    const int ah = tid & 1;
    int grow = GATHER ? ridx[ar] : (mBase + ar);
    const bool aok = (!GATHER) || (grow >= 0);
    const float* ap = A + (size_t)(aok ? grow : 0) * 256 + ah * 8;
    const int ag   = ar & 7;
    const int am16 = ar >> 4;
    const int ahi8 = (ar >> 3) & 1;

    const int bx16 = blockIdx.x * 16;
    const uint32_t smb = smem_u32(sm);

    const int warp_m = wid & 3;
    const int warp_n = wid >> 2;

    float acc[2][8][4];
    #pragma unroll
    for (int i = 0; i < 2; i++)
        #pragma unroll
        for (int j = 0; j < 8; j++)
            #pragma unroll
            for (int t = 0; t < 4; t++) acc[i][j][t] = 0.f;

    auto stageA = [&](int buf, const float4* v) {
        float* AHI = sm + buf * A_STG;
        float* ALO = AHI + 2048;
        #pragma unroll
        for (int q = 0; q < 2; q++) {
            int base = ((ah * 8 + am16) * 32 + ag * 4) * 4 + (ahi8 + 2 * q);
            float h0, l0, h1, l1, h2, l2, h3, l3;
            tf32_split(v[q].x, h0, l0);
            tf32_split(v[q].y, h1, l1);
            tf32_split(v[q].z, h2, l2);
            tf32_split(v[q].w, h3, l3);
            AHI[base + 0]  = h0;  ALO[base + 0]  = l0;
            AHI[base + 4]  = h1;  ALO[base + 4]  = l1;
            AHI[base + 8]  = h2;  ALO[base + 8]  = l2;
            AHI[base + 12] = h3;  ALO[base + 12] = l3;
        }
    };
    auto stageB = [&](int buf, int kb) {
        uint32_t dbase = smb + (SM_B0 + buf * B_STG) * 4;
        #pragma unroll
        for (int i = 0; i < 4; i++) {
            int t    = tid + i * 256;
            int ln   = t & 31;
            int n8l  = (t >> 5) & 15;
            int k8l  = t >> 9;
            const float4* src = g_wfrag +
                ((size_t)mat * 1024 + (size_t)(kb * 2 + k8l) * 32 + bx16 + n8l) * 32 + ln;
            CP_ASYNC16(dbase + (uint32_t)t * 16, (const void*)src);
        }
        CP_COMMIT();
    };

    // prologue: chunk 0
    {
        float4 av[2];
        #pragma unroll
        for (int q = 0; q < 2; q++)
            av[q] = aok ? *(const float4*)(ap + q * 4) : make_float4(0.f, 0.f, 0.f, 0.f);
        stageA(0, av);
        stageB(0, 0);
        CP_WAIT0();
        __syncthreads();
    }

    for (int kb = 0; kb < 16; kb++) {
        const int p = kb & 1;
        float4 nv[2];
        if (kb < 15) {
            stageB(p ^ 1, kb + 1);
            #pragma unroll
            for (int q = 0; q < 2; q++)
                nv[q] = aok ? *(const float4*)(ap + (kb + 1) * 16 + q * 4)
                            : make_float4(0.f, 0.f, 0.f, 0.f);
        }

        const float* AHI = sm + p * A_STG;
        const float* ALO = AHI + 2048;
        const float* BST = sm + SM_B0 + p * B_STG;
        #pragma unroll
        for (int k8 = 0; k8 < 2; k8++) {
            uint32_t ahf[2][4], alf[2][4];
            #pragma unroll
            for (int i = 0; i < 2; i++) {
                int m16 = warp_m * 2 + i;
                int off = ((k8 * 8 + m16) * 32 + lane) * 4;
                *(uint4*)ahf[i] = *(const uint4*)(AHI + off);
                *(uint4*)alf[i] = *(const uint4*)(ALO + off);
            }
            #pragma unroll
            for (int jq = 0; jq < 2; jq++) {
                float4 bf[4];
                #pragma unroll
                for (int jj = 0; jj < 4; jj++) {
                    int off = ((k8 * 16 + warp_n * 8 + jq * 4 + jj) * 32 + lane) * 4;
                    bf[jj] = *(const float4*)(BST + off);
                }
                // term hi*hi  (RAW distance 8)
                #pragma unroll
                for (int jj = 0; jj < 4; jj++)
                    #pragma unroll
                    for (int i = 0; i < 2; i++)
                        mma_tf32(acc[i][jq * 4 + jj], ahf[i],
                                 __float_as_uint(bf[jj].x), __float_as_uint(bf[jj].y));
                // term hi*lo
                #pragma unroll
                for (int jj = 0; jj < 4; jj++)
                    #pragma unroll
                    for (int i = 0; i < 2; i++)
                        mma_tf32(acc[i][jq * 4 + jj], ahf[i],
                                 __float_as_uint(bf[jj].z), __float_as_uint(bf[jj].w));
                // term lo*hi
                #pragma unroll
                for (int jj = 0; jj < 4; jj++)
                    #pragma unroll
                    for (int i = 0; i < 2; i++)
                        mma_tf32(acc[i][jq * 4 + jj], alf[i],
                                 __float_as_uint(bf[jj].x), __float_as_uint(bf[jj].y));
            }
        }

        if (kb < 15) {
            stageA(p ^ 1, nv);
            CP_WAIT0();
            __syncthreads();
        }
    }

    // ---- root: load W2 slice (128 cols x 8 cls) into smem buf0 (unused by chunk 15)
    float* W2s = sm;   // 1024 floats
    if (!GATHER) {
        if (tid < 256) {
            *(float4*)(W2s + tid * 4) = *(const float4*)(W2 + (size_t)nBase * 8 + tid * 4);
        }
        __syncthreads();
    }

    // ---- epilogue: bias + relu, store; root also accumulates partial logits
    const int g  = lane >> 2;
    const int tg = lane & 3;
    float plg[2][2][8];
    if (!GATHER) {
        #pragma unroll
        for (int i = 0; i < 2; i++)
            #pragma unroll
            for (int h = 0; h < 2; h++)
                #pragma unroll
                for (int cls = 0; cls < 8; cls++) plg[i][h][cls] = 0.f;
    }

    #pragma unroll
    for (int i = 0; i < 2; i++) {
        int rl0 = warp_m * 32 + i * 16 + g;
        int rl1 = rl0 + 8;
        int r0, r1;
        if (GATHER) { r0 = ridx[rl0]; r1 = ridx[rl1]; }
        else        { r0 = mBase + rl0; r1 = mBase + rl1; }
        #pragma unroll
        for (int j = 0; j < 8; j++) {
            int colL = warp_n * 64 + j * 8 + tg * 2;
            int col  = nBase + colL;
            float bv0 = __ldg(bias + col);
            float bv1 = __ldg(bias + col + 1);
            float2 v0 = make_float2(fmaxf(acc[i][j][0] + bv0, 0.f),
                                    fmaxf(acc[i][j][1] + bv1, 0.f));
            float2 v1 = make_float2(fmaxf(acc[i][j][2] + bv0, 0.f),
                                    fmaxf(acc[i][j][3] + bv1, 0.f));
            if (!GATHER) {
                *(float2*)(Out + (size_t)r0 * 256 + col) = v0;
                *(float2*)(Out + (size_t)r1 * 256 + col) = v1;
                *(float2*)(g_h + (size_t)r0 * 256 + col) = v0;
                *(float2*)(g_h + (size_t)r1 * 256 + col) = v1;
                const float* w0 = W2s + colL * 8;
                const float* w1 = w0 + 8;
                #pragma unroll
                for (int cls = 0; cls < 8; cls++) {
                    plg[i][0][cls] += v0.x * w0[cls] + v0.y * w1[cls];
                    plg[i][1][cls] += v1.x * w0[cls] + v1.y * w1[cls];
                }
            } else {
                if (r0 >= 0) *(float2*)(Out + (size_t)r0 * 256 + col) = v0;
                if (r1 >= 0) *(float2*)(Out + (size_t)r1 * 256 + col) = v1;
            }
        }
    }

    if (!GATHER) {
        // reduce plg over the 4 tg-lanes (lane = 4*g + tg): xor 1 then 2
        #pragma unroll
        for (int i = 0; i < 2; i++)
            #pragma unroll
            for (int h = 0; h < 2; h++)
                #pragma unroll
                for (int cls = 0; cls < 8; cls++) {
                    float v = plg[i][h][cls];
                    v += __shfl_xor_sync(0xffffffffu, v, 1);
                    v += __shfl_xor_sync(0xffffffffu, v, 2);
                    plg[i][h][cls] = v;
                }
        if (tg == 0) {
            int q = blockIdx.x * 2 + warp_n;
            #pragma unroll
            for (int i = 0; i < 2; i++) {
                int r0 = mBase + warp_m * 32 + i * 16 + g;
                float* p0 = &g_plog[q][r0][0];
                *(float4*)(p0)     = *(float4*)&plg[i][0][0];
                *(float4*)(p0 + 4) = *(float4*)&plg[i][0][4];
                float* p1 = &g_plog[q][r0 + 8][0];
                *(float4*)(p1)     = *(float4*)&plg[i][1][0];
                *(float4*)(p1 + 4) = *(float4*)&plg[i][1][4];
            }
        }
    }
}

// ---------------------------------------------------------------------------
// Routing: sum 4 partial-logit quarters, softmax, tau-mask argmax, compact.
// One thread per sample.
// ---------------------------------------------------------------------------
__global__ __launch_bounds__(256)
void route_kernel(const float* __restrict__ b2, const float* __restrict__ tau,
                  float* __restrict__ outLogits, float* __restrict__ outDepth)
{
    const int s = blockIdx.x * 256 + threadIdx.x;
    float lg[8];
    #pragma unroll
    for (int j = 0; j < 8; j++) lg[j] = __ldg(b2 + j);
    #pragma unroll
    for (int q = 0; q < 4; q++) {
        float4 p0 = *(const float4*)&g_plog[q][s][0];
        float4 p1 = *(const float4*)&g_plog[q][s][4];
        lg[0] += p0.x; lg[1] += p0.y; lg[2] += p0.z; lg[3] += p0.w;
        lg[4] += p1.x; lg[5] += p1.y; lg[6] += p1.z; lg[7] += p1.w;
    }
    float mx = -1e30f;
    #pragma unroll
    for (int j = 0; j < 8; j++) mx = fmaxf(mx, lg[j]);
    float e[8], ss = 0.f;
    #pragma unroll
    for (int j = 0; j < 8; j++) { e[j] = expf(lg[j] - mx); ss += e[j]; }
    float inv = 1.0f / ss;
    int best = -1; float bp = -1.f;
    #pragma unroll
    for (int j = 0; j < 8; j++) {
        float pj = e[j] * inv;
        if (pj >= __ldg(tau + j) && pj > bp) { bp = pj; best = j; }
    }
    float* lo = outLogits + (size_t)s * 8;
    *(float4*)(lo)     = make_float4(lg[0], lg[1], lg[2], lg[3]);
    *(float4*)(lo + 4) = make_float4(lg[4], lg[5], lg[6], lg[7]);
    outDepth[s] = (best >= 0) ? 1.0f : 0.0f;
    if (best >= 0) {
        int pos = atomicAdd(&g_cnt[best], 1);
        g_idx[best * Bn + pos] = s;
    }
}

// ---------------------------------------------------------------------------
// Expert head over compacted lists.
// ---------------------------------------------------------------------------
__global__ __launch_bounds__(256)
void expert_head(const float* __restrict__ Hbuf,
                 const float* __restrict__ Wc2, const float* __restrict__ bc2,
                 float* __restrict__ outLogits)
{
    const int c    = blockIdx.z;
    const int cnt  = g_cnt[c];
    const int base = blockIdx.y * 128;
    if (base >= cnt) return;

    __shared__ float Wst[8][256];
    __shared__ float bcs[8];
    const int tid = threadIdx.x;
    const float* W = Wc2 + (size_t)c * 2048;
    for (int i = tid; i < 2048; i += 256) Wst[i & 7][i >> 3] = W[i];
    if (tid < 8) bcs[tid] = bc2[c * 8 + tid];
    __syncthreads();

    const int wid = tid >> 5, lane = tid & 31;

    for (int grp = 0; grp < 4; grp++) {
        const int gib = base + wid * 16 + grp * 4;
        int s_0 = (gib + 0 < cnt) ? g_idx[c * Bn + gib + 0] : -1;
        int s_1 = (gib + 1 < cnt) ? g_idx[c * Bn + gib + 1] : -1;
        int s_2 = (gib + 2 < cnt) ? g_idx[c * Bn + gib + 2] : -1;
        int s_3 = (gib + 3 < cnt) ? g_idx[c * Bn + gib + 3] : -1;
        if (s_0 < 0) continue;

        float a0[8], a1[8], a2[8], a3[8];
        #pragma unroll
        for (int j = 0; j < 8; j++) a0[j] = a1[j] = a2[j] = a3[j] = 0.f;
        #pragma unroll
        for (int t = 0; t < 8; t++) {
            int col = t * 32 + lane;
            float w[8];
            #pragma unroll
            for (int j = 0; j < 8; j++) w[j] = Wst[j][col];
            float h0 = Hbuf[(size_t)s_0 * 256 + col];
            float h1 = (s_1 >= 0) ? Hbuf[(size_t)s_1 * 256 + col] : 0.f;
            float h2 = (s_2 >= 0) ? Hbuf[(size_t)s_2 * 256 + col] : 0.f;
            float h3 = (s_3 >= 0) ? Hbuf[(size_t)s_3 * 256 + col] : 0.f;
            #pragma unroll
            for (int j = 0; j < 8; j++) {
                a0[j] += h0 * w[j]; a1[j] += h1 * w[j];
                a2[j] += h2 * w[j]; a3[j] += h3 * w[j];
            }
        }
        #pragma unroll
        for (int j = 0; j < 8; j++) {
            #pragma unroll
            for (int off = 16; off; off >>= 1) {
                a0[j] += __shfl_xor_sync(0xffffffffu, a0[j], off);
                a1[j] += __shfl_xor_sync(0xffffffffu, a1[j], off);
                a2[j] += __shfl_xor_sync(0xffffffffu, a2[j], off);
                a3[j] += __shfl_xor_sync(0xffffffffu, a3[j], off);
            }
        }
        if (lane < 4) {
            int s = (lane == 0) ? s_0 : (lane == 1) ? s_1 : (lane == 2) ? s_2 : s_3;
            if (s >= 0) {
                float* lo = outLogits + (size_t)s * 8;
                #pragma unroll
                for (int j = 0; j < 8; j++) {
                    float v = (lane == 0) ? a0[j] : (lane == 1) ? a1[j] : (lane == 2) ? a2[j] : a3[j];
                    lo[j] = v + bcs[j];
                }
            }
        }
    }
}

// ---------------------------------------------------------------------------
extern "C" void kernel_launch(void* const* d_in, const int* in_sizes, int n_in,
                              void* d_out, int out_size)
{
    const float* x   = (const float*)d_in[0];
    const float* W1  = (const float*)d_in[1];
    const float* b1  = (const float*)d_in[2];
    const float* W2  = (const float*)d_in[3];
    const float* b2  = (const float*)d_in[4];
    const float* Wc1 = (const float*)d_in[5];
    const float* bc1 = (const float*)d_in[6];
    const float* Wc2 = (const float*)d_in[7];
    const float* bc2 = (const float*)d_in[8];
    const float* tau = (const float*)d_in[9];

    float* out       = (float*)d_out;
    float* outLogits = out;
    float* outH      = out + (size_t)Bn * Cc;
    float* outDepth  = out + (size_t)Bn * (Cc + Hh);

    static bool attr_done = false;
    if (!attr_done) {
        cudaFuncSetAttribute(gemm_mma<false>, cudaFuncAttributeMaxDynamicSharedMemorySize, SMEM_BYTES);
        cudaFuncSetAttribute(gemm_mma<true>,  cudaFuncAttributeMaxDynamicSharedMemorySize, SMEM_BYTES);
        attr_done = true;
    }

    zero_cnt_kernel<<<1, 32>>>();

    // One-time W fragment split (W1 + 8 experts)
    split_wfrag<<<(9 * 32768) / 256, 256>>>(W1, Wc1);

    // Root: h = relu(x @ W1 + b1) -> outH + g_h, fused partial logits -> g_plog
    gemm_mma<false><<<dim3(2, Bn / 128, 1), 256, SMEM_BYTES>>>(x, b1, W2, outH);

    // Routing from partial logits
    route_kernel<<<Bn / 256, 256>>>(b2, tau, outLogits, outDepth);

    // Expert dense: gather from g_h, write routed rows of outH
    gemm_mma<true><<<dim3(2, Bn / 128, Cc), 256, SMEM_BYTES>>>(nullptr, bc1, nullptr, outH);

    // Expert head: overwrite logits for routed rows
    expert_head<<<dim3(1, Bn / 128, Cc), 256>>>(outH, Wc2, bc2, outLogits);
}